// round 7
// baseline (speedup 1.0000x reference)
#include <cuda_runtime.h>

// Problem constants
#define Bc 64
#define Kc 5
#define Hc 320
#define Wc 320
#define Nc (Hc * Wc)        // 102400 pixels per (b,k)
#define NGc (Nc / 4)        // 25600 float4 groups
#define BPB 25              // blocks per batch; each block owns 1024 groups
#define THREADS 256
#define TOTAL_BLOCKS (Bc * BPB)
#define NACC 23             // 5*(S,I,XS,XF) + spsum + tabs + tfg
#define ROW 24              // scratch row stride (floats)

// Per-block partial sums: [b*BPB+block][ROW]. Overwritten every launch.
__device__ float g_scratch[TOTAL_BLOCKS * ROW];
// Last-block-done counter. atomicInc with limit TOTAL_BLOCKS-1 wraps to 0 after
// exactly TOTAL_BLOCKS increments -> self-resetting across graph replays.
__device__ unsigned int g_cnt = 0;

// Per-element update. 3 MUFU (EX2, RCP, LG2): ~23us of MUFU-pipe time chip-wide,
// fma pipe ~21us, DRAM ~25us -- co-designed so memory is the binding pipe.
// BCE identity: sum max(x,0) = 0.5*(sum x + sum |x|) -> no per-k softplus acc.
__device__ __forceinline__ void elem(float x, float fg,
                                     float& S, float& I, float& XS, float& XF,
                                     float& spsum, float& tabs)
{
    const float t  = fabsf(x);
    const float e  = __expf(-t);                 // FMUL + MUFU.EX2
    const float u  = 1.0f + e;
    const float rc = __fdividef(1.0f, u);        // MUFU.RCP
    const float p  = (x >= 0.0f) ? rc : (1.0f - rc);   // sigmoid(x)
    const float sp = __logf(u);                  // log1p(e) = MUFU.LG2 + FMUL

    spsum += sp;
    tabs  += t;
    S     += p;
    I      = fmaf(p, fg, I);
    XS    += x;
    XF     = fmaf(x, fg, XF);
}

#define ELEM4(xv, fgv, k) \
    elem((xv).x, (fgv).x, acc[(k)*4+0], acc[(k)*4+1], acc[(k)*4+2], acc[(k)*4+3], acc[20], acc[21]); \
    elem((xv).y, (fgv).y, acc[(k)*4+0], acc[(k)*4+1], acc[(k)*4+2], acc[(k)*4+3], acc[20], acc[21]); \
    elem((xv).z, (fgv).z, acc[(k)*4+0], acc[(k)*4+1], acc[(k)*4+2], acc[(k)*4+3], acc[20], acc[21]); \
    elem((xv).w, (fgv).w, acc[(k)*4+0], acc[(k)*4+1], acc[(k)*4+2], acc[(k)*4+3], acc[20], acc[21]);

__global__ __launch_bounds__(THREADS)
void hung_fused(const float* __restrict__ slot, const float* __restrict__ tgt,
                float* __restrict__ out)
{
    const int b = blockIdx.y;
    const int tid = threadIdx.x;

    float acc[NACC];
#pragma unroll
    for (int i = 0; i < NACC; i++) acc[i] = 0.0f;

    const float4* tg4 = reinterpret_cast<const float4*>(tgt) + (size_t)b * NGc;
    const float4* sl4 = reinterpret_cast<const float4*>(slot) + (size_t)b * Kc * NGc;

    const int base = blockIdx.x * (NGc / BPB);   // 1024 groups per block

    // Two iterations; each explicitly batches 12 independent LDG.128s before
    // any compute (MLP=12). unroll 1 stops ptxas from merging iterations into
    // a 24-deep front batch (L1tex-queue contention, R4 = 54us); the named
    // values force enough registers that the loads really overlap (R5's
    // regs=48 allocation serialized them, 3.3TB/s).
#pragma unroll 1
    for (int it = 0; it < 2; it++) {
        const int g0 = base + it * (2 * THREADS) + tid;
        const int g1 = g0 + THREADS;

        const float4 fgA = __ldg(&tg4[g0]);
        const float4 fgB = __ldg(&tg4[g1]);
        float4 xa[Kc], xb[Kc];
#pragma unroll
        for (int k = 0; k < Kc; k++) {
            xa[k] = __ldg(&sl4[(size_t)k * NGc + g0]);
            xb[k] = __ldg(&sl4[(size_t)k * NGc + g1]);
        }

        acc[22] += ((fgA.x + fgA.y) + (fgA.z + fgA.w))
                 + ((fgB.x + fgB.y) + (fgB.z + fgB.w));   // tfg
#pragma unroll
        for (int k = 0; k < Kc; k++) {
            ELEM4(xa[k], fgA, k)
            ELEM4(xb[k], fgB, k)
        }
    }

    // Block reduction: warp shuffle then cross-warp via shared (deterministic).
#pragma unroll
    for (int i = 0; i < NACC; i++) {
        float v = acc[i];
#pragma unroll
        for (int o = 16; o > 0; o >>= 1) v += __shfl_xor_sync(0xffffffffu, v, o);
        acc[i] = v;
    }
    __shared__ float sm[THREADS / 32][NACC];
    __shared__ float colsum[NACC];
    const int warp = tid >> 5, lane = tid & 31;
    if (lane == 0) {
#pragma unroll
        for (int i = 0; i < NACC; i++) sm[warp][i] = acc[i];
    }
    __syncthreads();
    if (tid < NACC) {
        float s = 0.0f;
#pragma unroll
        for (int w = 0; w < THREADS / 32; w++) s += sm[w][tid];
        colsum[tid] = s;
    }
    __syncthreads();

    // Thread 0 publishes this block's partials and bumps the done-counter.
    // Stores + release fence + atomic all from one thread => formally ordered.
    __shared__ unsigned int s_last;
    if (tid == 0) {
        float* dst = &g_scratch[((size_t)b * BPB + blockIdx.x) * ROW];
#pragma unroll
        for (int i = 0; i < NACC; i++) dst[i] = colsum[i];
        __threadfence();
        s_last = (atomicInc(&g_cnt, TOTAL_BLOCKS - 1) == TOTAL_BLOCKS - 1) ? 1u : 0u;
    }
    __syncthreads();
    if (s_last == 0u) return;

    // ---- Winner block: finalize. Runs after all hot-loop registers are dead,
    // so it does not raise the kernel's register peak. ~150KB, L2-resident. ----
    __shared__ float sa[Bc][ROW];
    __shared__ float red[Bc];
    for (int s = tid; s < Bc * ROW; s += THREADS) {
        const int bb = s / ROW, i = s - bb * ROW;
        float v = 0.0f;
        if (i < NACC) {
#pragma unroll
            for (int j = 0; j < BPB; j++)
                v += __ldcg(&g_scratch[((size_t)bb * BPB + j) * ROW + i]);
        }
        sa[bb][i] = v;
    }
    __syncthreads();

    if (tid < Bc) {
        const float* a = sa[tid];
        const float Tfg   = a[22];
        const float Tbg   = (float)Nc - Tfg;
        const float spsum = a[20];
        const float tabs  = a[21];
        float sumXS = 0.0f, sumXF = 0.0f;
        float best = 3.4e38f, selXS = 0.0f, selXF = 0.0f;
#pragma unroll
        for (int k = 0; k < Kc; k++) {
            const float S  = a[k*4+0];
            const float I  = a[k*4+1];
            const float XS = a[k*4+2];
            const float XF = a[k*4+3];
            const float Ib = S - I;
            const float cfg = 1.0f - I  / (S + Tfg - I  + 1e-6f);
            const float cbg = 1.0f - Ib / (S + Tbg - Ib + 1e-6f);
            const float score = cfg - cbg;   // perm cost differs only by this term
            if (score < best) { best = score; selXS = XS; selXF = XF; }  // ties -> smallest k
            sumXS += XS; sumXF += XF;
        }
        const float Ctot = spsum + 0.5f * (sumXS + tabs);  // sum max(x,0) + sum softplus
        // loss_b = Ctot - [XF_k0 + sum_{k!=k0}(XS_k - XF_k)]
        red[tid] = Ctot - sumXS + sumXF + selXS - 2.0f * selXF;
    }
    __syncthreads();
    if (tid == 0) {
        float tot = 0.0f;
#pragma unroll
        for (int i = 0; i < Bc; i++) tot += red[i];
        out[0] = tot * (1.0f / ((float)Bc * (float)Kc * (float)Nc));
    }
}

extern "C" void kernel_launch(void* const* d_in, const int* in_sizes, int n_in,
                              void* d_out, int out_size)
{
    // metadata order: fg_logits (unused by reference), slot_logits, target
    const float* slot = (const float*)d_in[1];
    const float* tgt  = (const float*)d_in[2];
    float* out = (float*)d_out;

    dim3 grid(BPB, Bc);
    hung_fused<<<grid, THREADS>>>(slot, tgt, out);
}

// round 8
// speedup vs baseline: 1.2731x; 1.2731x over previous
#include <cuda_runtime.h>

// Problem constants
#define Bc 64
#define Kc 5
#define Hc 320
#define Wc 320
#define Nc (Hc * Wc)        // 102400 pixels per (b,k)
#define NGc (Nc / 4)        // 25600 float4 groups
#define BPB 25              // blocks per batch; each block owns 1024 groups
#define THREADS 256
#define TOTAL_BLOCKS (Bc * BPB)
#define NACC 23             // 5*(S,I,XS,XF) + spsum + tabs + tfg
#define ROW 24              // scratch row stride (floats)

// Per-block partial sums: [b*BPB+block][ROW]. Overwritten every launch.
__device__ float g_scratch[TOTAL_BLOCKS * ROW];
// Per-batch losses + last-block counter for the finalize kernel.
__device__ float g_loss[Bc];
// atomicInc with limit Bc-1 wraps to 0 after exactly Bc increments ->
// self-resetting across graph replays.
__device__ unsigned int g_cnt = 0;

// Per-element update. 3 MUFU (EX2, RCP, LG2): ~23us of MUFU-pipe time chip-wide,
// fma pipe ~21us, DRAM ~25us -- memory is the binding pipe.
// BCE identity: sum max(x,0) = 0.5*(sum x + sum |x|) -> no per-k softplus acc.
__device__ __forceinline__ void elem(float x, float fg,
                                     float& S, float& I, float& XS, float& XF,
                                     float& spsum, float& tabs)
{
    const float t  = fabsf(x);
    const float e  = __expf(-t);                 // FMUL + MUFU.EX2
    const float u  = 1.0f + e;
    const float rc = __fdividef(1.0f, u);        // MUFU.RCP
    const float p  = (x >= 0.0f) ? rc : (1.0f - rc);   // sigmoid(x)
    const float sp = __logf(u);                  // log1p(e) = MUFU.LG2 + FMUL

    spsum += sp;
    tabs  += t;
    S     += p;
    I      = fmaf(p, fg, I);
    XS    += x;
    XF     = fmaf(x, fg, XF);
}

#define ELEM4(xv, fgv, k) \
    elem((xv).x, (fgv).x, acc[(k)*4+0], acc[(k)*4+1], acc[(k)*4+2], acc[(k)*4+3], acc[20], acc[21]); \
    elem((xv).y, (fgv).y, acc[(k)*4+0], acc[(k)*4+1], acc[(k)*4+2], acc[(k)*4+3], acc[20], acc[21]); \
    elem((xv).z, (fgv).z, acc[(k)*4+0], acc[(k)*4+1], acc[(k)*4+2], acc[(k)*4+3], acc[20], acc[21]); \
    elem((xv).w, (fgv).w, acc[(k)*4+0], acc[(k)*4+1], acc[(k)*4+2], acc[(k)*4+3], acc[20], acc[21]);

// Hot-loop kernel: MUST stay standalone. Fusing any tail onto it re-triggers
// ptxas' 48-reg allocation, which serializes the 12-load batch (R5/R7: 46-48us
// at 3.3-3.5TB/s vs this kernel's ~31us).
__global__ __launch_bounds__(THREADS)
void hung_main(const float* __restrict__ slot, const float* __restrict__ tgt)
{
    const int b = blockIdx.y;
    const int tid = threadIdx.x;

    float acc[NACC];
#pragma unroll
    for (int i = 0; i < NACC; i++) acc[i] = 0.0f;

    const float4* tg4 = reinterpret_cast<const float4*>(tgt) + (size_t)b * NGc;
    const float4* sl4 = reinterpret_cast<const float4*>(slot) + (size_t)b * Kc * NGc;

    const int base = blockIdx.x * (NGc / BPB);   // 1024 groups per block

    // Two iterations; each explicitly batches 12 independent LDG.128s before
    // any compute (MLP=12). unroll 1 stops ptxas from merging iterations into
    // a 24-deep front batch (L1tex-queue contention, R4 = 54us).
#pragma unroll 1
    for (int it = 0; it < 2; it++) {
        const int g0 = base + it * (2 * THREADS) + tid;
        const int g1 = g0 + THREADS;

        const float4 fgA = __ldg(&tg4[g0]);
        const float4 fgB = __ldg(&tg4[g1]);
        float4 xa[Kc], xb[Kc];
#pragma unroll
        for (int k = 0; k < Kc; k++) {
            xa[k] = __ldg(&sl4[(size_t)k * NGc + g0]);
            xb[k] = __ldg(&sl4[(size_t)k * NGc + g1]);
        }

        acc[22] += ((fgA.x + fgA.y) + (fgA.z + fgA.w))
                 + ((fgB.x + fgB.y) + (fgB.z + fgB.w));   // tfg
#pragma unroll
        for (int k = 0; k < Kc; k++) {
            ELEM4(xa[k], fgA, k)
            ELEM4(xb[k], fgB, k)
        }
    }

    // Block reduction: warp shuffle then cross-warp via shared (deterministic).
#pragma unroll
    for (int i = 0; i < NACC; i++) {
        float v = acc[i];
#pragma unroll
        for (int o = 16; o > 0; o >>= 1) v += __shfl_xor_sync(0xffffffffu, v, o);
        acc[i] = v;
    }
    __shared__ float sm[THREADS / 32][NACC];
    const int warp = tid >> 5, lane = tid & 31;
    if (lane == 0) {
#pragma unroll
        for (int i = 0; i < NACC; i++) sm[warp][i] = acc[i];
    }
    __syncthreads();
    if (tid < NACC) {
        float s = 0.0f;
#pragma unroll
        for (int w = 0; w < THREADS / 32; w++) s += sm[w][tid];
        g_scratch[((size_t)b * BPB + blockIdx.x) * ROW + tid] = s;
    }
}

// Parallel finalize: 64 blocks (one per batch) x 64 threads.
// Each block reduces its 25x23 partials (~2.3KB, L2-hot) and computes the
// per-batch loss; the LAST block (atomic counter) sums the 64 losses.
// Previous single-block finalize was 7.7us of pure latency.
__global__ __launch_bounds__(64)
void hung_final(float* __restrict__ out)
{
    const int b = blockIdx.x;
    const int tid = threadIdx.x;

    __shared__ float sa[NACC];
    __shared__ unsigned int s_last;

    if (tid < NACC) {
        float v = 0.0f;
#pragma unroll
        for (int j = 0; j < BPB; j++)
            v += g_scratch[((size_t)b * BPB + j) * ROW + tid];
        sa[tid] = v;
    }
    __syncthreads();

    if (tid == 0) {
        const float* a = sa;
        const float Tfg   = a[22];
        const float Tbg   = (float)Nc - Tfg;
        const float spsum = a[20];
        const float tabs  = a[21];
        float sumXS = 0.0f, sumXF = 0.0f;
        float best = 3.4e38f, selXS = 0.0f, selXF = 0.0f;
#pragma unroll
        for (int k = 0; k < Kc; k++) {
            const float S  = a[k*4+0];
            const float I  = a[k*4+1];
            const float XS = a[k*4+2];
            const float XF = a[k*4+3];
            const float Ib = S - I;
            const float cfg = 1.0f - I  / (S + Tfg - I  + 1e-6f);
            const float cbg = 1.0f - Ib / (S + Tbg - Ib + 1e-6f);
            const float score = cfg - cbg;   // perm cost differs only by this term
            if (score < best) { best = score; selXS = XS; selXF = XF; }  // ties -> smallest k
            sumXS += XS; sumXF += XF;
        }
        const float Ctot = spsum + 0.5f * (sumXS + tabs);  // sum max(x,0) + sum softplus
        // loss_b = Ctot - [XF_k0 + sum_{k!=k0}(XS_k - XF_k)]
        g_loss[b] = Ctot - sumXS + sumXF + selXS - 2.0f * selXF;
        __threadfence();
        s_last = (atomicInc(&g_cnt, Bc - 1) == Bc - 1) ? 1u : 0u;
    }
    __syncthreads();
    if (s_last == 0u) return;

    // Last block: sum the 64 per-batch losses (L2-resident).
    float l = (tid < Bc) ? __ldcg(&g_loss[tid]) : 0.0f;
#pragma unroll
    for (int o = 16; o > 0; o >>= 1) l += __shfl_xor_sync(0xffffffffu, l, o);
    __shared__ float wsum[2];
    if ((tid & 31) == 0) wsum[tid >> 5] = l;
    __syncthreads();
    if (tid == 0)
        out[0] = (wsum[0] + wsum[1]) * (1.0f / ((float)Bc * (float)Kc * (float)Nc));
}

extern "C" void kernel_launch(void* const* d_in, const int* in_sizes, int n_in,
                              void* d_out, int out_size)
{
    // metadata order: fg_logits (unused by reference), slot_logits, target
    const float* slot = (const float*)d_in[1];
    const float* tgt  = (const float*)d_in[2];
    float* out = (float*)d_out;

    dim3 grid(BPB, Bc);
    hung_main<<<grid, THREADS>>>(slot, tgt);
    hung_final<<<Bc, 64>>>(out);
}